// round 15
// baseline (speedup 1.0000x reference)
#include <cuda_runtime.h>
#include <stdint.h>

#define NC   151          // classes incl. background
#define CM1  150
#define DIM  2048
#define NB   128          // images
#define NP   512          // pairs per image
#define CAP  16           // max absent classes with precomputed corr rows
#define CHW  16           // float4 per chunk row (64 floats)
#define NCHUNK (DIM / 4 / CHW)   // 32
#define TPB  1024

// table-build decomposition: 16 classes x 128 d per block
#define TB_CLS   16
#define TB_CGRP  10       // ceil(151/16)
#define TB_D     128
#define TB_BLOCKS (TB_CGRP * 2 * (DIM / TB_D))   // 320

// ---------------- device scratch ----------------
__device__ float  g_sym[NC * NC];
__device__ float  g_T0[NC * DIM];
__device__ float  g_T1[NC * DIM];
__device__ int    g_abs_cnt[NB];
__device__ int    g_abs_list[NB * CM1];
__device__ float4 g_corr0[NB * CAP * (DIM / 4)];  // lin_w[:, e-1]     per absent e
__device__ float4 g_corr1[NB * CAP * (DIM / 4)];  // lin_w[:, 150+e-1] per absent e
__device__ const float* g_lwp;                    // used ONLY by noinline fallback

// ---------------- float4 helpers ----------------
__device__ __forceinline__ float4 f4add(float4 a, float4 b) {
    return make_float4(a.x + b.x, a.y + b.y, a.z + b.z, a.w + b.w);
}
__device__ __forceinline__ float4 f4fms(float s, float4 a, float4 acc) {
    acc.x = fmaf(-s, a.x, acc.x); acc.y = fmaf(-s, a.y, acc.y);
    acc.z = fmaf(-s, a.z, acc.z); acc.w = fmaf(-s, a.w, acc.w);
    return acc;
}

// int64-vs-int32 detection (all pair values >= 1, little-endian)
__device__ __forceinline__ int pairs_is64(const int* p32) { return (p32[1] == 0) ? 1 : 0; }

// ---------------- kernel 1: ALL prep in one launch (disjoint block roles) ----------------
// block 0            : sym table (+ publish lin_w pointer for fallback)
// blocks 1..NB       : per-image absent lists + correction-row precompute
// next TB_BLOCKS     : T0/T1 table build (native coalesced lin_w reads)
__global__ void __launch_bounds__(128) k_pre(const void* __restrict__ pairs_v,
                                             const float* __restrict__ score,
                                             const float* __restrict__ w,
                                             const float* __restrict__ lb) {
    __shared__ float tile[TB_D][33];          // j-tile staging (tables role)
    __shared__ float ssym[TB_CLS][CM1 + 2];
    __shared__ int flags[NC];
    __shared__ int s_list[CAP];
    __shared__ int s_cnt;

    const int* p32 = (const int*)pairs_v;
    int tid = threadIdx.x;

    if (blockIdx.x == 0) {
        if (tid == 0) g_lwp = w;
#pragma unroll 4
        for (int idx = tid; idx < NC * NC; idx += 128) {
            int c = idx / NC, e = idx % NC;
            g_sym[idx] = 0.5f * (score[c * NC + e] + score[e * NC + c]);
        }
    } else if (blockIdx.x <= NB) {
        int b = blockIdx.x - 1;
        int is64 = pairs_is64(p32);
        for (int i = tid; i < NC; i += 128) flags[i] = 0;
        __syncthreads();
#pragma unroll 4
        for (int i = tid; i < 2 * NP; i += 128) {
            size_t ei = (size_t)b * 2 * NP + i;
            flags[p32[ei << is64]] = 1;
        }
        __syncthreads();
        if (tid == 0) {
            int cnt = 0;
            for (int e = 1; e < NC; ++e)
                if (!flags[e]) {
                    g_abs_list[b * CM1 + cnt] = e;
                    if (cnt < CAP) s_list[cnt] = e;
                    ++cnt;
                }
            g_abs_cnt[b] = cnt;
            s_cnt = cnt;
        }
        __syncthreads();
        // precompute correction weight rows for this image's absent classes
        int kcf = s_cnt < CAP ? s_cnt : CAP;
        float* c0 = (float*)g_corr0;
        float* c1 = (float*)g_corr1;
        for (int idx = tid; idx < kcf * DIM; idx += 128) {
            int k = idx >> 11, d = idx & (DIM - 1);
            int e = s_list[k];
            size_t dst = ((size_t)b * CAP + k) * DIM + d;
            c0[dst] = w[(size_t)d * 600 + (e - 1)];
            c1[dst] = w[(size_t)d * 600 + (CM1 + e - 1)];
        }
    } else {
        // ---- T0/T1 table build, native lin_w reads ----
        int t = blockIdx.x - (NB + 1);        // 0..319
        int cg    = t % TB_CGRP;
        int which = (t / TB_CGRP) & 1;
        int dwin  = t / (TB_CGRP * 2);        // 0..15
        int cBase = cg * TB_CLS;
        int d0 = dwin * TB_D;
        int wbase = which * CM1;

        for (int idx = tid; idx < TB_CLS * CM1; idx += 128) {
            int ci = idx / CM1, j = idx - ci * CM1;
            int c = cBase + ci;
            ssym[ci][j] = (c < NC)
                ? 0.5f * (score[c * NC + (j + 1)] + score[(j + 1) * NC + c]) : 0.f;
        }
        __syncthreads();

        float acc[TB_CLS];
#pragma unroll
        for (int ci = 0; ci < TB_CLS; ++ci) acc[ci] = 0.f;

        for (int jb = 0; jb < CM1; jb += 32) {
            int wt = (CM1 - jb < 32) ? (CM1 - jb) : 32;
#pragma unroll
            for (int rep = 0; rep < 32; ++rep) {
                int idx = tid + 128 * rep;
                int dl = idx >> 5, jl = idx & 31;
                tile[dl][jl] = (jl < wt) ? w[(size_t)(d0 + dl) * 600 + wbase + jb + jl] : 0.f;
            }
            __syncthreads();
            for (int jl = 0; jl < wt; ++jl) {
                float wv = tile[tid][jl];
                int j = jb + jl;
#pragma unroll
                for (int ci = 0; ci < TB_CLS; ++ci)
                    acc[ci] = fmaf(ssym[ci][j], wv, acc[ci]);
            }
            __syncthreads();
        }

        int d = d0 + tid;
        float hb = 0.5f * lb[d];
        float* Tdst = which ? g_T1 : g_T0;
#pragma unroll
        for (int ci = 0; ci < TB_CLS; ++ci) {
            int c = cBase + ci;
            if (c >= NC) continue;
            float v = acc[ci] + hb;
            if (c >= 1) v += w[(size_t)d * 600 + 300 + which * CM1 + c - 1];
            Tdst[(size_t)c * DIM + d] = v;
        }
    }
}

// ---------------- rare exact fallback (noinline; only place that touches g_lwp) ----------------
__device__ __noinline__ float4 fallback_corr(float4 v, int b, int p0, int p1,
                                             int cb, int j, int cnt) {
    const float* lw = g_lwp;
    int dbase = (cb + j) * 4;
    for (int k = CAP; k < cnt; ++k) {
        int e = g_abs_list[b * CM1 + k];
        float c0 = g_sym[p0 * NC + e];
        float c1 = g_sym[p1 * NC + e];
#pragma unroll
        for (int dd = 0; dd < 4; ++dd) {
            float a  = lw[(size_t)(dbase + dd) * 600 + (e - 1)];
            float bb = lw[(size_t)(dbase + dd) * 600 + (CM1 + e - 1)];
            float* vc = ((float*)&v) + dd;
            *vc = fmaf(-c0, a, fmaf(-c1, bb, *vc));
        }
    }
    return v;
}

// ---------------- kernel 2: persistent gather/add ----------------
// grid 296 (2 blocks/SM), 1024 threads, ~81.5KB dynamic smem each.
// Corrections read straight from g_corr globals (immediate base, kc-gated).
__global__ void __launch_bounds__(TPB, 2) k_main(const void* __restrict__ pairs_v,
                                                 float* __restrict__ out) {
    extern __shared__ float4 smem[];
    float4* s0 = smem;                       // NC*CHW
    float4* s1 = s0 + NC * CHW;              // NC*CHW
    int* sp = (int*)(s1 + NC * CHW);         // 2*NP = 1024
    int* slist = sp + 2 * NP;                // CAP
    __shared__ int scnt;

    const int* p32 = (const int*)pairs_v;
    int is64 = pairs_is64(p32);
    int tid = threadIdx.x;
    const float4* T04 = (const float4*)g_T0;
    const float4* T14 = (const float4*)g_T1;
    float4* out4 = (float4*)out;

    const int nitems = NCHUNK * NB;          // 4096
    int start = (int)(((long)nitems * blockIdx.x) / gridDim.x);
    int end   = (int)(((long)nitems * (blockIdx.x + 1)) / gridDim.x);
    int cur_chunk = -1;

    for (int item = start; item < end; ++item) {
        int chunk = item >> 7;               // item / NB
        int b = item & (NB - 1);
        int cb = chunk * CHW;

        __syncthreads();                     // protect smem reuse from prior item
        if (chunk != cur_chunk) {
            for (int idx = tid; idx < NC * CHW; idx += TPB) {
                int c = idx / CHW, j = idx % CHW;
                s0[idx] = T04[(size_t)c * (DIM / 4) + cb + j];
                s1[idx] = T14[(size_t)c * (DIM / 4) + cb + j];
            }
            cur_chunk = chunk;
        }
        sp[tid] = p32[((size_t)b * 2 * NP + tid) << is64];
        if (tid < CAP) slist[tid] = g_abs_list[b * CM1 + tid];
        if (tid == 0) scnt = g_abs_cnt[b];
        __syncthreads();

        int cnt = scnt;
        int kc = cnt < CAP ? cnt : CAP;

        int j = tid & (CHW - 1), sub = tid >> 4;   // sub in 0..63
        int cbase = (b * CAP) * (DIM / 4) + cb + j;  // g_corr base index (k step = DIM/4)
#pragma unroll 4
        for (int it = 0; it < NP / 64; ++it) {
            int p = it * 64 + sub;
            int p0 = sp[2 * p], p1 = sp[2 * p + 1];
            float4 v = f4add(s0[p0 * CHW + j], s1[p1 * CHW + j]);
            for (int k = 0; k < kc; ++k) {
                int e = slist[k];
                v = f4fms(g_sym[p0 * NC + e], g_corr0[cbase + k * (DIM / 4)], v);
                v = f4fms(g_sym[p1 * NC + e], g_corr1[cbase + k * (DIM / 4)], v);
            }
            if (cnt > CAP) v = fallback_corr(v, b, p0, p1, cb, j, cnt);
            __stcs(&out4[(size_t)(b * NP + p) * (DIM / 4) + cb + j], v);
        }
    }
}

// ---------------- launch ----------------
static const size_t SMEM_MAIN =
    (size_t)(2 * NC * CHW) * sizeof(float4) + (2 * NP + CAP) * sizeof(int);

extern "C" void kernel_launch(void* const* d_in, const int* in_sizes, int n_in,
                              void* d_out, int out_size) {
    const void*  pairs = d_in[0];
    const float* score = (const float*)d_in[1];
    const float* lw    = (const float*)d_in[2];
    const float* lb    = (const float*)d_in[3];
    float* out = (float*)d_out;
    (void)in_sizes; (void)n_in; (void)out_size;

    cudaFuncSetAttribute(k_main, cudaFuncAttributeMaxDynamicSharedMemorySize, (int)SMEM_MAIN);

    k_pre <<<NB + 1 + TB_BLOCKS, 128>>>(pairs, score, lw, lb);
    k_main<<<296, TPB, SMEM_MAIN>>>(pairs, out);
}

// round 16
// speedup vs baseline: 1.0142x; 1.0142x over previous
#include <cuda_runtime.h>
#include <stdint.h>

#define NC   151          // classes incl. background
#define CM1  150
#define DIM  2048
#define NB   128          // images
#define NP   512          // pairs per image
#define CAP  16           // max absent classes with precomputed corr rows
#define CHW  16           // float4 per chunk row (64 floats)
#define NCHUNK (DIM / 4 / CHW)   // 32
#define TPB  1024

// table-build decomposition: 16 classes x 128 d per block
#define TB_CLS   16
#define TB_CGRP  10       // ceil(151/16)
#define TB_D     128
#define TB_BLOCKS (TB_CGRP * 2 * (DIM / TB_D))   // 320

// ---------------- device scratch ----------------
__device__ float  g_sym[NC * NC];
__device__ float  g_T0[NC * DIM];
__device__ float  g_T1[NC * DIM];
__device__ int    g_abs_cnt[NB];
__device__ int    g_abs_list[NB * CM1];
__device__ float4 g_corr0[NB * CAP * (DIM / 4)];  // lin_w[:, e-1]     per absent e
__device__ float4 g_corr1[NB * CAP * (DIM / 4)];  // lin_w[:, 150+e-1] per absent e
__device__ const float* g_lwp;                    // used ONLY by noinline fallback

// ---------------- float4 helpers ----------------
__device__ __forceinline__ float4 f4add(float4 a, float4 b) {
    return make_float4(a.x + b.x, a.y + b.y, a.z + b.z, a.w + b.w);
}
__device__ __forceinline__ float4 f4fms(float s, float4 a, float4 acc) {
    acc.x = fmaf(-s, a.x, acc.x); acc.y = fmaf(-s, a.y, acc.y);
    acc.z = fmaf(-s, a.z, acc.z); acc.w = fmaf(-s, a.w, acc.w);
    return acc;
}

// int64-vs-int32 detection (all pair values >= 1, little-endian)
__device__ __forceinline__ int pairs_is64(const int* p32) { return (p32[1] == 0) ? 1 : 0; }

// ---------------- kernel 1: ALL prep in one launch (disjoint block roles) ----------------
// block 0            : sym table (+ publish lin_w pointer for fallback)
// blocks 1..NB       : per-image absent lists + correction-row precompute
// next TB_BLOCKS     : T0/T1 table build (native coalesced lin_w reads)
__global__ void __launch_bounds__(128) k_pre(const void* __restrict__ pairs_v,
                                             const float* __restrict__ score,
                                             const float* __restrict__ w,
                                             const float* __restrict__ lb) {
    __shared__ float tile[TB_D][33];          // j-tile staging (tables role)
    __shared__ float ssym[TB_CLS][CM1 + 2];
    __shared__ int flags[NC];
    __shared__ int s_list[CAP];
    __shared__ int s_cnt;

    const int* p32 = (const int*)pairs_v;
    int tid = threadIdx.x;

    if (blockIdx.x == 0) {
        if (tid == 0) g_lwp = w;
#pragma unroll 4
        for (int idx = tid; idx < NC * NC; idx += 128) {
            int c = idx / NC, e = idx % NC;
            g_sym[idx] = 0.5f * (score[c * NC + e] + score[e * NC + c]);
        }
    } else if (blockIdx.x <= NB) {
        int b = blockIdx.x - 1;
        int is64 = pairs_is64(p32);
        for (int i = tid; i < NC; i += 128) flags[i] = 0;
        __syncthreads();
#pragma unroll 4
        for (int i = tid; i < 2 * NP; i += 128) {
            size_t ei = (size_t)b * 2 * NP + i;
            flags[p32[ei << is64]] = 1;
        }
        __syncthreads();
        if (tid == 0) {
            int cnt = 0;
            for (int e = 1; e < NC; ++e)
                if (!flags[e]) {
                    g_abs_list[b * CM1 + cnt] = e;
                    if (cnt < CAP) s_list[cnt] = e;
                    ++cnt;
                }
            g_abs_cnt[b] = cnt;
            s_cnt = cnt;
        }
        __syncthreads();
        // precompute correction weight rows for this image's absent classes
        int kcf = s_cnt < CAP ? s_cnt : CAP;
        float* c0 = (float*)g_corr0;
        float* c1 = (float*)g_corr1;
        for (int idx = tid; idx < kcf * DIM; idx += 128) {
            int k = idx >> 11, d = idx & (DIM - 1);
            int e = s_list[k];
            size_t dst = ((size_t)b * CAP + k) * DIM + d;
            c0[dst] = w[(size_t)d * 600 + (e - 1)];
            c1[dst] = w[(size_t)d * 600 + (CM1 + e - 1)];
        }
    } else {
        // ---- T0/T1 table build, native lin_w reads ----
        int t = blockIdx.x - (NB + 1);        // 0..319
        int cg    = t % TB_CGRP;
        int which = (t / TB_CGRP) & 1;
        int dwin  = t / (TB_CGRP * 2);        // 0..15
        int cBase = cg * TB_CLS;
        int d0 = dwin * TB_D;
        int wbase = which * CM1;

        for (int idx = tid; idx < TB_CLS * CM1; idx += 128) {
            int ci = idx / CM1, j = idx - ci * CM1;
            int c = cBase + ci;
            ssym[ci][j] = (c < NC)
                ? 0.5f * (score[c * NC + (j + 1)] + score[(j + 1) * NC + c]) : 0.f;
        }
        __syncthreads();

        float acc[TB_CLS];
#pragma unroll
        for (int ci = 0; ci < TB_CLS; ++ci) acc[ci] = 0.f;

        for (int jb = 0; jb < CM1; jb += 32) {
            int wt = (CM1 - jb < 32) ? (CM1 - jb) : 32;
#pragma unroll
            for (int rep = 0; rep < 32; ++rep) {
                int idx = tid + 128 * rep;
                int dl = idx >> 5, jl = idx & 31;
                tile[dl][jl] = (jl < wt) ? w[(size_t)(d0 + dl) * 600 + wbase + jb + jl] : 0.f;
            }
            __syncthreads();
            for (int jl = 0; jl < wt; ++jl) {
                float wv = tile[tid][jl];
                int j = jb + jl;
#pragma unroll
                for (int ci = 0; ci < TB_CLS; ++ci)
                    acc[ci] = fmaf(ssym[ci][j], wv, acc[ci]);
            }
            __syncthreads();
        }

        int d = d0 + tid;
        float hb = 0.5f * lb[d];
        float* Tdst = which ? g_T1 : g_T0;
#pragma unroll
        for (int ci = 0; ci < TB_CLS; ++ci) {
            int c = cBase + ci;
            if (c >= NC) continue;
            float v = acc[ci] + hb;
            if (c >= 1) v += w[(size_t)d * 600 + 300 + which * CM1 + c - 1];
            Tdst[(size_t)c * DIM + d] = v;
        }
    }
}

// ---------------- rare exact fallback (noinline; only place that touches g_lwp) ----------------
__device__ __noinline__ float4 fallback_corr(float4 v, int b, int p0, int p1,
                                             int cb, int j, int cnt) {
    const float* lw = g_lwp;
    int dbase = (cb + j) * 4;
    for (int k = CAP; k < cnt; ++k) {
        int e = g_abs_list[b * CM1 + k];
        float c0 = g_sym[p0 * NC + e];
        float c1 = g_sym[p1 * NC + e];
#pragma unroll
        for (int dd = 0; dd < 4; ++dd) {
            float a  = lw[(size_t)(dbase + dd) * 600 + (e - 1)];
            float bb = lw[(size_t)(dbase + dd) * 600 + (CM1 + e - 1)];
            float* vc = ((float*)&v) + dd;
            *vc = fmaf(-c0, a, fmaf(-c1, bb, *vc));
        }
    }
    return v;
}

// ---------------- kernel 2: persistent gather/add (hot loop = R14, byte-identical) ----------------
// grid 296 (2 blocks/SM), 1024 threads, ~89.7KB dynamic smem each.
// Corrections staged g_corr -> wa/wb smem in the kc-gated setup slot (same shape as R14's WT fill).
__global__ void __launch_bounds__(TPB, 2) k_main(const void* __restrict__ pairs_v,
                                                 float* __restrict__ out) {
    extern __shared__ float4 smem[];
    float4* s0 = smem;                       // NC*CHW
    float4* s1 = s0 + NC * CHW;              // NC*CHW
    float4* wa = s1 + NC * CHW;              // CAP*CHW
    float4* wb = wa + CAP * CHW;             // CAP*CHW
    int* sp = (int*)(wb + CAP * CHW);        // 2*NP = 1024
    int* slist = sp + 2 * NP;                // CAP
    __shared__ int scnt;

    const int* p32 = (const int*)pairs_v;
    int is64 = pairs_is64(p32);
    int tid = threadIdx.x;
    const float4* T04 = (const float4*)g_T0;
    const float4* T14 = (const float4*)g_T1;
    float4* out4 = (float4*)out;

    const int nitems = NCHUNK * NB;          // 4096
    int start = (int)(((long)nitems * blockIdx.x) / gridDim.x);
    int end   = (int)(((long)nitems * (blockIdx.x + 1)) / gridDim.x);
    int cur_chunk = -1;

    for (int item = start; item < end; ++item) {
        int chunk = item >> 7;               // item / NB
        int b = item & (NB - 1);
        int cb = chunk * CHW;

        __syncthreads();                     // protect smem reuse from prior item
        if (chunk != cur_chunk) {
            for (int idx = tid; idx < NC * CHW; idx += TPB) {
                int c = idx / CHW, j = idx % CHW;
                s0[idx] = T04[(size_t)c * (DIM / 4) + cb + j];
                s1[idx] = T14[(size_t)c * (DIM / 4) + cb + j];
            }
            cur_chunk = chunk;
        }
        sp[tid] = p32[((size_t)b * 2 * NP + tid) << is64];
        if (tid < CAP) slist[tid] = g_abs_list[b * CM1 + tid];
        if (tid == 0) scnt = g_abs_cnt[b];
        __syncthreads();

        int cnt = scnt;
        int kc = cnt < CAP ? cnt : CAP;
        for (int idx = tid; idx < kc * CHW; idx += TPB) {
            int k = idx / CHW, j = idx % CHW;
            wa[idx] = g_corr0[(size_t)(b * CAP + k) * (DIM / 4) + cb + j];
            wb[idx] = g_corr1[(size_t)(b * CAP + k) * (DIM / 4) + cb + j];
        }
        if (kc) __syncthreads();

        int j = tid & (CHW - 1), sub = tid >> 4;   // sub in 0..63
#pragma unroll 4
        for (int it = 0; it < NP / 64; ++it) {
            int p = it * 64 + sub;
            int p0 = sp[2 * p], p1 = sp[2 * p + 1];
            float4 v = f4add(s0[p0 * CHW + j], s1[p1 * CHW + j]);
            for (int k = 0; k < kc; ++k) {
                int e = slist[k];
                v = f4fms(g_sym[p0 * NC + e], wa[k * CHW + j], v);
                v = f4fms(g_sym[p1 * NC + e], wb[k * CHW + j], v);
            }
            if (cnt > CAP) v = fallback_corr(v, b, p0, p1, cb, j, cnt);
            __stcs(&out4[(size_t)(b * NP + p) * (DIM / 4) + cb + j], v);
        }
    }
}

// ---------------- launch ----------------
static const size_t SMEM_MAIN =
    (size_t)(2 * NC * CHW + 2 * CAP * CHW) * sizeof(float4) + (2 * NP + CAP) * sizeof(int);

extern "C" void kernel_launch(void* const* d_in, const int* in_sizes, int n_in,
                              void* d_out, int out_size) {
    const void*  pairs = d_in[0];
    const float* score = (const float*)d_in[1];
    const float* lw    = (const float*)d_in[2];
    const float* lb    = (const float*)d_in[3];
    float* out = (float*)d_out;
    (void)in_sizes; (void)n_in; (void)out_size;

    cudaFuncSetAttribute(k_main, cudaFuncAttributeMaxDynamicSharedMemorySize, (int)SMEM_MAIN);

    k_pre <<<NB + 1 + TB_BLOCKS, 128>>>(pairs, score, lw, lb);
    k_main<<<296, TPB, SMEM_MAIN>>>(pairs, out);
}

// round 17
// speedup vs baseline: 1.2403x; 1.2230x over previous
#include <cuda_runtime.h>
#include <stdint.h>

#define NC   151          // classes incl. background
#define CM1  150
#define DIM  2048
#define NB   128          // images
#define NP   512          // pairs per image
#define CAP  16           // max absent classes with precomputed corr rows
#define CHW  16           // float4 per chunk row (64 floats)
#define NCHUNK (DIM / 4 / CHW)   // 32
#define TPB  1024

// table-build decomposition: 16 classes x 128 d per block
#define TB_CLS   16
#define TB_CGRP  10       // ceil(151/16)
#define TB_D     128
#define TB_BLOCKS (TB_CGRP * 2 * (DIM / TB_D))   // 320

// ---------------- device scratch ----------------
__device__ float  g_sym[NC * NC];
__device__ float  g_T0[NC * DIM];
__device__ float  g_T1[NC * DIM];
__device__ int    g_abs_cnt[NB];
__device__ int    g_abs_list[NB * CM1];
__device__ float4 g_corr0[NB * CAP * (DIM / 4)];  // lin_w[:, e-1]     per absent e
__device__ float4 g_corr1[NB * CAP * (DIM / 4)];  // lin_w[:, 150+e-1] per absent e

// ---------------- float4 helpers ----------------
__device__ __forceinline__ float4 f4add(float4 a, float4 b) {
    return make_float4(a.x + b.x, a.y + b.y, a.z + b.z, a.w + b.w);
}
__device__ __forceinline__ float4 f4fms(float s, float4 a, float4 acc) {
    acc.x = fmaf(-s, a.x, acc.x); acc.y = fmaf(-s, a.y, acc.y);
    acc.z = fmaf(-s, a.z, acc.z); acc.w = fmaf(-s, a.w, acc.w);
    return acc;
}

// int64-vs-int32 detection (all pair values >= 1, little-endian)
__device__ __forceinline__ int pairs_is64(const int* p32) { return (p32[1] == 0) ? 1 : 0; }

// ---------------- kernel 1: ALL prep in one launch (disjoint block roles) ----------------
// block 0            : sym table
// blocks 1..NB       : per-image absent lists + correction-row precompute
// next TB_BLOCKS     : T0/T1 table build (native coalesced lin_w reads)
__global__ void __launch_bounds__(128) k_pre(const void* __restrict__ pairs_v,
                                             const float* __restrict__ score,
                                             const float* __restrict__ w,
                                             const float* __restrict__ lb) {
    __shared__ float tile[TB_D][33];          // j-tile staging (tables role)
    __shared__ float ssym[TB_CLS][CM1 + 2];
    __shared__ int flags[NC];
    __shared__ int s_list[CAP];
    __shared__ int s_cnt;

    const int* p32 = (const int*)pairs_v;
    int tid = threadIdx.x;

    if (blockIdx.x == 0) {
#pragma unroll 4
        for (int idx = tid; idx < NC * NC; idx += 128) {
            int c = idx / NC, e = idx % NC;
            g_sym[idx] = 0.5f * (score[c * NC + e] + score[e * NC + c]);
        }
    } else if (blockIdx.x <= NB) {
        int b = blockIdx.x - 1;
        int is64 = pairs_is64(p32);
        for (int i = tid; i < NC; i += 128) flags[i] = 0;
        __syncthreads();
#pragma unroll 4
        for (int i = tid; i < 2 * NP; i += 128) {
            size_t ei = (size_t)b * 2 * NP + i;
            flags[p32[ei << is64]] = 1;
        }
        __syncthreads();
        if (tid == 0) {
            int cnt = 0;
            for (int e = 1; e < NC; ++e)
                if (!flags[e]) {
                    g_abs_list[b * CM1 + cnt] = e;
                    if (cnt < CAP) s_list[cnt] = e;
                    ++cnt;
                }
            g_abs_cnt[b] = cnt;
            s_cnt = cnt;
        }
        __syncthreads();
        // precompute correction weight rows for this image's absent classes
        int kcf = s_cnt < CAP ? s_cnt : CAP;
        float* c0 = (float*)g_corr0;
        float* c1 = (float*)g_corr1;
        for (int idx = tid; idx < kcf * DIM; idx += 128) {
            int k = idx >> 11, d = idx & (DIM - 1);
            int e = s_list[k];
            size_t dst = ((size_t)b * CAP + k) * DIM + d;
            c0[dst] = w[(size_t)d * 600 + (e - 1)];
            c1[dst] = w[(size_t)d * 600 + (CM1 + e - 1)];
        }
    } else {
        // ---- T0/T1 table build, native lin_w reads ----
        int t = blockIdx.x - (NB + 1);        // 0..319
        int cg    = t % TB_CGRP;
        int which = (t / TB_CGRP) & 1;
        int dwin  = t / (TB_CGRP * 2);        // 0..15
        int cBase = cg * TB_CLS;
        int d0 = dwin * TB_D;
        int wbase = which * CM1;

        for (int idx = tid; idx < TB_CLS * CM1; idx += 128) {
            int ci = idx / CM1, j = idx - ci * CM1;
            int c = cBase + ci;
            ssym[ci][j] = (c < NC)
                ? 0.5f * (score[c * NC + (j + 1)] + score[(j + 1) * NC + c]) : 0.f;
        }
        __syncthreads();

        float acc[TB_CLS];
#pragma unroll
        for (int ci = 0; ci < TB_CLS; ++ci) acc[ci] = 0.f;

        for (int jb = 0; jb < CM1; jb += 32) {
            int wt = (CM1 - jb < 32) ? (CM1 - jb) : 32;
#pragma unroll
            for (int rep = 0; rep < 32; ++rep) {
                int idx = tid + 128 * rep;
                int dl = idx >> 5, jl = idx & 31;
                tile[dl][jl] = (jl < wt) ? w[(size_t)(d0 + dl) * 600 + wbase + jb + jl] : 0.f;
            }
            __syncthreads();
            for (int jl = 0; jl < wt; ++jl) {
                float wv = tile[tid][jl];
                int j = jb + jl;
#pragma unroll
                for (int ci = 0; ci < TB_CLS; ++ci)
                    acc[ci] = fmaf(ssym[ci][j], wv, acc[ci]);
            }
            __syncthreads();
        }

        int d = d0 + tid;
        float hb = 0.5f * lb[d];
        float* Tdst = which ? g_T1 : g_T0;
#pragma unroll
        for (int ci = 0; ci < TB_CLS; ++ci) {
            int c = cBase + ci;
            if (c >= NC) continue;
            float v = acc[ci] + hb;
            if (c >= 1) v += w[(size_t)d * 600 + 300 + which * CM1 + c - 1];
            Tdst[(size_t)c * DIM + d] = v;
        }
    }
}

// ---------------- kernel 2: persistent gather/add — NO lin_w reference anywhere ----------------
// grid 296 (2 blocks/SM), 1024 threads, ~89.7KB dynamic smem each.
// Corrections (k < CAP) staged g_corr -> wa/wb smem in the kc-gated setup slot.
// Overflow corrections (cnt > CAP) handled exactly by k_fix afterwards.
__global__ void __launch_bounds__(TPB, 2) k_main(const void* __restrict__ pairs_v,
                                                 float* __restrict__ out) {
    extern __shared__ float4 smem[];
    float4* s0 = smem;                       // NC*CHW
    float4* s1 = s0 + NC * CHW;              // NC*CHW
    float4* wa = s1 + NC * CHW;              // CAP*CHW
    float4* wb = wa + CAP * CHW;             // CAP*CHW
    int* sp = (int*)(wb + CAP * CHW);        // 2*NP = 1024
    int* slist = sp + 2 * NP;                // CAP
    __shared__ int scnt;

    const int* p32 = (const int*)pairs_v;
    int is64 = pairs_is64(p32);
    int tid = threadIdx.x;
    const float4* T04 = (const float4*)g_T0;
    const float4* T14 = (const float4*)g_T1;
    float4* out4 = (float4*)out;

    const int nitems = NCHUNK * NB;          // 4096
    int start = (int)(((long)nitems * blockIdx.x) / gridDim.x);
    int end   = (int)(((long)nitems * (blockIdx.x + 1)) / gridDim.x);
    int cur_chunk = -1;

    for (int item = start; item < end; ++item) {
        int chunk = item >> 7;               // item / NB
        int b = item & (NB - 1);
        int cb = chunk * CHW;

        __syncthreads();                     // protect smem reuse from prior item
        if (chunk != cur_chunk) {
            for (int idx = tid; idx < NC * CHW; idx += TPB) {
                int c = idx / CHW, j = idx % CHW;
                s0[idx] = T04[(size_t)c * (DIM / 4) + cb + j];
                s1[idx] = T14[(size_t)c * (DIM / 4) + cb + j];
            }
            cur_chunk = chunk;
        }
        sp[tid] = p32[((size_t)b * 2 * NP + tid) << is64];
        if (tid < CAP) slist[tid] = g_abs_list[b * CM1 + tid];
        if (tid == 0) scnt = g_abs_cnt[b];
        __syncthreads();

        int cnt = scnt;
        int kc = cnt < CAP ? cnt : CAP;
        for (int idx = tid; idx < kc * CHW; idx += TPB) {
            int k = idx / CHW, j = idx % CHW;
            wa[idx] = g_corr0[(size_t)(b * CAP + k) * (DIM / 4) + cb + j];
            wb[idx] = g_corr1[(size_t)(b * CAP + k) * (DIM / 4) + cb + j];
        }
        if (kc) __syncthreads();

        int j = tid & (CHW - 1), sub = tid >> 4;   // sub in 0..63
#pragma unroll 4
        for (int it = 0; it < NP / 64; ++it) {
            int p = it * 64 + sub;
            int p0 = sp[2 * p], p1 = sp[2 * p + 1];
            float4 v = f4add(s0[p0 * CHW + j], s1[p1 * CHW + j]);
            for (int k = 0; k < kc; ++k) {
                int e = slist[k];
                v = f4fms(g_sym[p0 * NC + e], wa[k * CHW + j], v);
                v = f4fms(g_sym[p1 * NC + e], wb[k * CHW + j], v);
            }
            __stcs(&out4[(size_t)(b * NP + p) * (DIM / 4) + cb + j], v);
        }
    }
}

// ---------------- kernel 3: exact overflow patch (cnt > CAP; practically never runs) ----------
// 128 blocks; each checks its image's absent count and returns immediately when <= CAP.
__global__ void k_fix(const void* __restrict__ pairs_v,
                      const float* __restrict__ lw,
                      float* __restrict__ out) {
    int b = blockIdx.x;
    int cnt = g_abs_cnt[b];
    if (cnt <= CAP) return;                  // always taken in practice
    const int* p32 = (const int*)pairs_v;
    int is64 = pairs_is64(p32);
    int tid = threadIdx.x;
    for (int p = 0; p < NP; ++p) {
        int p0 = p32[((size_t)(b * 2 * NP + 2 * p)) << is64];
        int p1 = p32[((size_t)(b * 2 * NP + 2 * p + 1)) << is64];
        for (int d = tid; d < DIM; d += blockDim.x) {
            float corr = 0.f;
            for (int k = CAP; k < cnt; ++k) {
                int e = g_abs_list[b * CM1 + k];
                corr += g_sym[p0 * NC + e] * lw[(size_t)d * 600 + (e - 1)]
                      + g_sym[p1 * NC + e] * lw[(size_t)d * 600 + (CM1 + e - 1)];
            }
            out[(size_t)(b * NP + p) * DIM + d] -= corr;
        }
    }
}

// ---------------- launch ----------------
static const size_t SMEM_MAIN =
    (size_t)(2 * NC * CHW + 2 * CAP * CHW) * sizeof(float4) + (2 * NP + CAP) * sizeof(int);

extern "C" void kernel_launch(void* const* d_in, const int* in_sizes, int n_in,
                              void* d_out, int out_size) {
    const void*  pairs = d_in[0];
    const float* score = (const float*)d_in[1];
    const float* lw    = (const float*)d_in[2];
    const float* lb    = (const float*)d_in[3];
    float* out = (float*)d_out;
    (void)in_sizes; (void)n_in; (void)out_size;

    cudaFuncSetAttribute(k_main, cudaFuncAttributeMaxDynamicSharedMemorySize, (int)SMEM_MAIN);

    k_pre <<<NB + 1 + TB_BLOCKS, 128>>>(pairs, score, lw, lb);
    k_main<<<296, TPB, SMEM_MAIN>>>(pairs, out);
    k_fix <<<NB, 128>>>(pairs, lw, out);
}